// round 11
// baseline (speedup 1.0000x reference)
#include <cuda_runtime.h>
#include <cstdint>

#define BB 2
#define NN 1024
#define CC 64
#define MI 8
#define TPB 256

// scratch: u[b,r,o] = sum_c x[b,r,c]*w1[o,c]  (512 KB) ; q[b,r] = 0.5*<w2,u_r>
__device__ __align__(16) float g_u[BB * NN * CC];
__device__ float g_q[BB * NN];

// ---------------- Phase 1: u = X @ W1^T, q = 0.5*u@w2 ----------------
__global__ __launch_bounds__(TPB) void uproj_kernel(
    const float* __restrict__ x, const float* __restrict__ w1,
    const float* __restrict__ w2) {
  __shared__ float wt[CC * 65];
  __shared__ float xs[4 * CC];
  __shared__ float qred[8];
  int tid = threadIdx.x;

  for (int idx = tid; idx < CC * CC; idx += TPB) {
    int o = idx >> 6, c = idx & 63;
    wt[c * 65 + o] = w1[idx];
  }
  xs[tid] = x[blockIdx.x * (4 * CC) + tid];
  __syncthreads();

  int rr = tid >> 6, o = tid & 63;
  float acc = 0.f;
#pragma unroll
  for (int c = 0; c < CC; c++)
    acc = fmaf(xs[rr * CC + c], wt[c * 65 + o], acc);
  g_u[blockIdx.x * (4 * CC) + tid] = acc;

  float v = acc * w2[o];
#pragma unroll
  for (int s = 16; s > 0; s >>= 1)
    v += __shfl_xor_sync(0xffffffffu, v, s);
  int warp = tid >> 5, lane = tid & 31;
  if (lane == 0) qred[warp] = v;
  __syncthreads();
  if (tid < 4)
    g_q[blockIdx.x * 4 + tid] = 0.5f * (qred[2 * tid] + qred[2 * tid + 1]);
}

// ---------------- Phase 2: scores + fused softmax ----------------
// relu(x) = (x+|x|)/2  =>
// score(b,i,j) = const_i + sum_o (0.5*w2[o])*|a_i[o]-u_j[o]| - q_j
// const_i cancels under softmax; a_i = u_i + b1; q_j = 0.5*<w2,u_j>.
// R5-R7 lesson: packed-f32x2 inline asm over indexed 64-bit accumulator
// arrays wedged the register allocator at the 128-reg cap -> hot-loop
// local spills -> 240-445 MB DRAM traffic. This version is plain scalar
// CUDA C: fabsf folds into FFMA |src| modifiers, live set ~50 regs.
__global__ __launch_bounds__(TPB, 2) void scores_kernel(
    const float* __restrict__ b1, const float* __restrict__ w2,
    float* __restrict__ out) {
  __shared__ __align__(16) float s_sc[MI * NN];  // 32 KB score staging
  __shared__ __align__(16) float na_s[MI * CC];  // -(u_i + b1)
  __shared__ __align__(16) float w2_s[CC];       // 0.5*w2
  __shared__ float red[MI * 8];

  int tid = threadIdx.x;
  int b = blockIdx.x >> 7;
  int i0 = (blockIdx.x & 127) * MI;

  if (tid < CC) w2_s[tid] = 0.5f * w2[tid];
  for (int idx = tid; idx < MI * CC; idx += TPB) {
    int ii = idx >> 6, o = idx & 63;
    na_s[idx] = -(g_u[(b * NN + i0 + ii) * CC + o] + b1[o]);
  }
  __syncthreads();

  const float4* ub4 = (const float4*)(g_u + (size_t)b * NN * CC);
  const float4* nap = (const float4*)na_s;   // 16 float4 per i-row
  const float4* w2p = (const float4*)w2_s;
  const float* qb = g_q + (size_t)b * NN;

#pragma unroll 1
  for (int jt = 0; jt < 4; jt++) {
    int j = jt * TPB + tid;
    const float4* up = ub4 + (size_t)j * 16;
    float acc[MI];
#pragma unroll
    for (int ii = 0; ii < MI; ii++) acc[ii] = 0.f;
#pragma unroll
    for (int k = 0; k < 16; k++) {       // 4 channels per k
      float4 uv = up[k];                 // LDG.128 (L2-resident u_j)
      float4 wv = w2p[k];                // LDS.128 broadcast
#pragma unroll
      for (int ii = 0; ii < MI; ii++) {
        float4 na = nap[ii * 16 + k];    // LDS.128 broadcast
        acc[ii] = fmaf(wv.x, fabsf(uv.x + na.x), acc[ii]);
        acc[ii] = fmaf(wv.y, fabsf(uv.y + na.y), acc[ii]);
        acc[ii] = fmaf(wv.z, fabsf(uv.z + na.z), acc[ii]);
        acc[ii] = fmaf(wv.w, fabsf(uv.w + na.w), acc[ii]);
      }
    }
    float qj = qb[j];
#pragma unroll
    for (int ii = 0; ii < MI; ii++)
      s_sc[ii * NN + j] = acc[ii] - qj;
  }
  __syncthreads();

  // ---- fused softmax over j (scores in SMEM) ----
  int warp = tid >> 5, lane = tid & 31;
  float rmax[MI], rinv[MI];

#pragma unroll
  for (int ii = 0; ii < MI; ii++) {
    float m = -1e30f;
#pragma unroll
    for (int jt = 0; jt < 4; jt++)
      m = fmaxf(m, s_sc[ii * NN + jt * TPB + tid]);
#pragma unroll
    for (int s = 16; s > 0; s >>= 1)
      m = fmaxf(m, __shfl_xor_sync(0xffffffffu, m, s));
    if (lane == 0) red[ii * 8 + warp] = m;
  }
  __syncthreads();
#pragma unroll
  for (int ii = 0; ii < MI; ii++) {
    float m = red[ii * 8];
#pragma unroll
    for (int w = 1; w < 8; w++) m = fmaxf(m, red[ii * 8 + w]);
    rmax[ii] = m;
  }
  __syncthreads();   // max-reads complete before red reuse

#pragma unroll
  for (int ii = 0; ii < MI; ii++) {
    float s = 0.f;
#pragma unroll
    for (int jt = 0; jt < 4; jt++) {
      int idx = ii * NN + jt * TPB + tid;
      float e = __expf(s_sc[idx] - rmax[ii]);
      s_sc[idx] = e;
      s += e;
    }
#pragma unroll
    for (int sh = 16; sh > 0; sh >>= 1)
      s += __shfl_xor_sync(0xffffffffu, s, sh);
    if (lane == 0) red[ii * 8 + warp] = s;
  }
  __syncthreads();
#pragma unroll
  for (int ii = 0; ii < MI; ii++) {
    float s = red[ii * 8];
#pragma unroll
    for (int w = 1; w < 8; w++) s += red[ii * 8 + w];
    rinv[ii] = 1.0f / s;
  }

  // coalesced stores: out[b, i0+ii, jt*256 + tid]
  float* ob = out + ((size_t)b * NN + i0) * NN;
#pragma unroll
  for (int ii = 0; ii < MI; ii++)
#pragma unroll
    for (int jt = 0; jt < 4; jt++)
      ob[ii * NN + jt * TPB + tid] = s_sc[ii * NN + jt * TPB + tid] * rinv[ii];
}

extern "C" void kernel_launch(void* const* d_in, const int* in_sizes, int n_in,
                              void* d_out, int out_size) {
  const float* x  = (const float*)d_in[0];   // [2,1024,64] f32
  const float* w1 = (const float*)d_in[1];   // [64,64]
  const float* b1 = (const float*)d_in[2];   // [64]
  const float* w2 = (const float*)d_in[3];   // [64]
  // d_in[4] = b2 : additive scalar, cancels under softmax — unused
  float* out = (float*)d_out;                // [2,1024,1024] f32

  uproj_kernel<<<(BB * NN) / 4, TPB>>>(x, w1, w2);
  scores_kernel<<<(BB * NN) / MI, TPB>>>(b1, w2, out);
}

// round 17
// speedup vs baseline: 7.0218x; 7.0218x over previous
#include <cuda_runtime.h>
#include <cstdint>

#define BB 2
#define NN 1024
#define CC 64
#define MI 8
#define TPB 256

// scratch (c-major transpose): u_T[c][b*NN+j]  (512 KB); q[b,r] = 0.5*<w2,u_r>
__device__ __align__(16) float g_ut[CC * BB * NN];
__device__ float g_q[BB * NN];

// ---------------- Phase 1: u = X @ W1^T (stored transposed), q ----------------
// grid = B*N/4 = 512 blocks, 256 threads. Block: 4 rows x 64 outputs.
__global__ __launch_bounds__(TPB) void uproj_kernel(
    const float* __restrict__ x, const float* __restrict__ w1,
    const float* __restrict__ w2) {
  __shared__ float wt[CC * 65];   // w1 transposed, padded
  __shared__ float xs[4 * CC];
  __shared__ float us[4 * CC];    // u staging for transposed store
  __shared__ float qred[8];
  int tid = threadIdx.x;

  for (int idx = tid; idx < CC * CC; idx += TPB) {
    int o = idx >> 6, c = idx & 63;
    wt[c * 65 + o] = w1[idx];
  }
  xs[tid] = x[blockIdx.x * (4 * CC) + tid];
  __syncthreads();

  int rr = tid >> 6, o = tid & 63;
  float acc = 0.f;
#pragma unroll
  for (int c = 0; c < CC; c++)
    acc = fmaf(xs[rr * CC + c], wt[c * 65 + o], acc);
  us[rr * CC + o] = acc;

  // q = 0.5 * sum_o w2[o]*u[r,o]
  float v = acc * w2[o];
#pragma unroll
  for (int s = 16; s > 0; s >>= 1)
    v += __shfl_xor_sync(0xffffffffu, v, s);
  int warp = tid >> 5, lane = tid & 31;
  if (lane == 0) qred[warp] = v;
  __syncthreads();
  if (tid < 4)
    g_q[blockIdx.x * 4 + tid] = 0.5f * (qred[2 * tid] + qred[2 * tid + 1]);

  // transposed store: g_ut[o][row0..row0+3] as one float4 (row0 = blk*4, %4==0)
  if (tid < CC) {
    int row0 = blockIdx.x * 4;
    float4 vv = make_float4(us[0 * CC + tid], us[1 * CC + tid],
                            us[2 * CC + tid], us[3 * CC + tid]);
    *(float4*)(g_ut + tid * (BB * NN) + row0) = vv;
  }
}

// ---------------- Phase 2: scores + fused softmax ----------------
// relu(x) = (x+|x|)/2 =>
// score(b,i,j) = const_i + sum_c (0.5*w2[c])*|a_i[c]-u_j[c]| - q_j
// const_i cancels under softmax; a_i = u_i + b1; q_j = 0.5*<w2,u_j>.
//
// R5-R11 lesson: fully-unrolled 16x8 inner body let ptxas hoist ~100+
// operand loads -> 128-reg peg -> hot-loop local spills -> 215-445 MB
// DRAM. Also row-major u made every LDG.128 32-way address-divergent
// (32 L1tex wavefronts). This version:
//   * u transposed (c-major) -> coalesced LDG.32, 1 wavefront
//   * a_i staged as na_t[c][8] -> 2x LDS.128 per channel for all 8 rows
//   * c-loop "#pragma unroll 4" bounds the hoist window -> ~60 live regs
__global__ __launch_bounds__(TPB, 2) void scores_kernel(
    const float* __restrict__ b1, const float* __restrict__ w2,
    float* __restrict__ out) {
  __shared__ __align__(16) float s_sc[MI * NN];  // 32 KB score staging
  __shared__ __align__(16) float na_t[CC * MI];  // -(u_i+b1), c-major [c][ii]
  __shared__ float w2_s[CC];                     // 0.5*w2
  __shared__ float red[MI * 8];

  int tid = threadIdx.x;
  int b = blockIdx.x >> 7;
  int i0 = (blockIdx.x & 127) * MI;

  if (tid < CC) w2_s[tid] = 0.5f * w2[tid];
  for (int idx = tid; idx < CC * MI; idx += TPB) {
    int c = idx >> 3, ii = idx & 7;
    na_t[idx] = -(g_ut[c * (BB * NN) + b * NN + i0 + ii] + b1[c]);
  }
  __syncthreads();

  const float* qb = g_q + (size_t)b * NN;

#pragma unroll 1
  for (int jt = 0; jt < 4; jt++) {
    int j = jt * TPB + tid;
    const float* up = g_ut + b * NN + j;   // stride BB*NN between channels
    float acc[MI];
#pragma unroll
    for (int ii = 0; ii < MI; ii++) acc[ii] = 0.f;
#pragma unroll 4
    for (int c = 0; c < CC; c++) {
      float uv = up[c << 11];              // LDG.32, coalesced across lanes
      float wc = w2_s[c];                  // LDS.32 broadcast
      float4 n0 = *(const float4*)&na_t[c * MI];      // LDS.128 broadcast
      float4 n1 = *(const float4*)&na_t[c * MI + 4];  // LDS.128 broadcast
      acc[0] = fmaf(wc, fabsf(uv + n0.x), acc[0]);
      acc[1] = fmaf(wc, fabsf(uv + n0.y), acc[1]);
      acc[2] = fmaf(wc, fabsf(uv + n0.z), acc[2]);
      acc[3] = fmaf(wc, fabsf(uv + n0.w), acc[3]);
      acc[4] = fmaf(wc, fabsf(uv + n1.x), acc[4]);
      acc[5] = fmaf(wc, fabsf(uv + n1.y), acc[5]);
      acc[6] = fmaf(wc, fabsf(uv + n1.z), acc[6]);
      acc[7] = fmaf(wc, fabsf(uv + n1.w), acc[7]);
    }
    float qj = qb[j];
#pragma unroll
    for (int ii = 0; ii < MI; ii++)
      s_sc[ii * NN + j] = acc[ii] - qj;
  }
  __syncthreads();

  // ---- fused softmax over j (scores in SMEM) ----
  int warp = tid >> 5, lane = tid & 31;
  float rmax[MI], rinv[MI];

#pragma unroll
  for (int ii = 0; ii < MI; ii++) {
    float m = -1e30f;
#pragma unroll
    for (int jt = 0; jt < 4; jt++)
      m = fmaxf(m, s_sc[ii * NN + jt * TPB + tid]);
#pragma unroll
    for (int s = 16; s > 0; s >>= 1)
      m = fmaxf(m, __shfl_xor_sync(0xffffffffu, m, s));
    if (lane == 0) red[ii * 8 + warp] = m;
  }
  __syncthreads();
#pragma unroll
  for (int ii = 0; ii < MI; ii++) {
    float m = red[ii * 8];
#pragma unroll
    for (int w = 1; w < 8; w++) m = fmaxf(m, red[ii * 8 + w]);
    rmax[ii] = m;
  }
  __syncthreads();   // max-reads complete before red reuse

#pragma unroll
  for (int ii = 0; ii < MI; ii++) {
    float s = 0.f;
#pragma unroll
    for (int jt = 0; jt < 4; jt++) {
      int idx = ii * NN + jt * TPB + tid;
      float e = __expf(s_sc[idx] - rmax[ii]);
      s_sc[idx] = e;
      s += e;
    }
#pragma unroll
    for (int sh = 16; sh > 0; sh >>= 1)
      s += __shfl_xor_sync(0xffffffffu, s, sh);
    if (lane == 0) red[ii * 8 + warp] = s;
  }
  __syncthreads();
#pragma unroll
  for (int ii = 0; ii < MI; ii++) {
    float s = red[ii * 8];
#pragma unroll
    for (int w = 1; w < 8; w++) s += red[ii * 8 + w];
    rinv[ii] = 1.0f / s;
  }

  // coalesced stores: out[b, i0+ii, jt*256 + tid]
  float* ob = out + ((size_t)b * NN + i0) * NN;
#pragma unroll
  for (int ii = 0; ii < MI; ii++)
#pragma unroll
    for (int jt = 0; jt < 4; jt++)
      ob[ii * NN + jt * TPB + tid] = s_sc[ii * NN + jt * TPB + tid] * rinv[ii];
}

extern "C" void kernel_launch(void* const* d_in, const int* in_sizes, int n_in,
                              void* d_out, int out_size) {
  const float* x  = (const float*)d_in[0];   // [2,1024,64] f32
  const float* w1 = (const float*)d_in[1];   // [64,64]
  const float* b1 = (const float*)d_in[2];   // [64]
  const float* w2 = (const float*)d_in[3];   // [64]
  // d_in[4] = b2 : additive scalar, cancels under softmax — unused
  float* out = (float*)d_out;                // [2,1024,1024] f32

  uproj_kernel<<<(BB * NN) / 4, TPB>>>(x, w1, w2);
  scores_kernel<<<(BB * NN) / MI, TPB>>>(b1, w2, out);
}